// round 5
// baseline (speedup 1.0000x reference)
#include <cuda_runtime.h>

// Problem constants (fixed by setup_inputs)
#define B_    16
#define CIN   64
#define COUT  64
#define H_    224
#define W_    224
#define PH    32
#define PW    32

#define THREADS 256
#define CO_PB 8                       // Cout per conv block
#define YSPLIT 2                      // PH split into 2 halves of 16 rows
#define CONV_BLOCKS (B_ * (COUT / CO_PB) * YSPLIT)   // 256
#define COPY_BLOCKS 1024
#define TOTAL_F4 ((B_ * COUT * H_ * W_) / 4)          // 12,845,056

#define ROWS_IN 18                    // 16 output rows + 2 halo
#define ROW_S  36                     // padded smem row stride
#define IN_SMEM (8 * ROWS_IN * ROW_S) // 5184 floats
#define W_SMEM  (8 * 8 * 9)           // 576 floats, layout [ci][k][co]

__global__ __launch_bounds__(THREADS, 4)
void inc_conv_fused(const float* __restrict__ in,
                    const float* __restrict__ wgt,
                    const float* __restrict__ bias,
                    const float* __restrict__ prev,
                    const int*   __restrict__ loc,
                    float* __restrict__ out)
{
    __shared__ float smem[IN_SMEM + W_SMEM];
    const int tid = threadIdx.x;
    const int bid = blockIdx.x;

    if (bid < CONV_BLOCKS) {
        // ------------- conv path: block = (batch, 8 Cout, 16-row half) -------------
        float (*in_s)[ROWS_IN][ROW_S] = (float (*)[ROWS_IN][ROW_S])smem;
        float* w_s = smem + IN_SMEM;

        const int b   = bid >> 4;
        const int rem = bid & 15;
        const int cob = (rem >> 1) * CO_PB;
        const int ys  = (rem & 1) * 16;
        const int y0  = loc[2 * b];
        const int x0  = loc[2 * b + 1];

        float acc[CO_PB][2];
        #pragma unroll
        for (int co = 0; co < CO_PB; co++) { acc[co][0] = 0.f; acc[co][1] = 0.f; }

        const int oyb = tid >> 5;   // 0..7
        const int ox  = tid & 31;   // 0..31

        for (int ci0 = 0; ci0 < CIN; ci0 += 8) {
            __syncthreads();
            // stage input: 8ci x 18 x 34 (zero-fill only low padded edges possible)
            for (int i = tid; i < 8 * ROWS_IN * 34; i += THREADS) {
                int ci = i / (ROWS_IN * 34);
                int rr = i % (ROWS_IN * 34);
                int r = rr / 34, c = rr % 34;
                int iy = y0 - 1 + ys + r;
                int ix = x0 - 1 + c;
                float v = 0.f;
                if (iy >= 0 && ix >= 0)
                    v = in[(((b * CIN) + ci0 + ci) * H_ + iy) * W_ + ix];
                in_s[ci][r][c] = v;
            }
            // stage weights transposed: w_s[(ci*9 + k)*8 + co]
            for (int i = tid; i < W_SMEM; i += THREADS) {
                int co = i & 7;
                int k  = (i >> 3) % 9;
                int ci = i / 72;
                w_s[(ci * 9 + k) * 8 + co] =
                    wgt[((cob + co) * CIN + ci0 + ci) * 9 + k];
            }
            __syncthreads();

            #pragma unroll
            for (int ci = 0; ci < 8; ci++) {
                #pragma unroll
                for (int kh = 0; kh < 3; kh++) {
                    float i0[3], i1[3];
                    #pragma unroll
                    for (int kw = 0; kw < 3; kw++) {
                        i0[kw] = in_s[ci][oyb + kh][ox + kw];
                        i1[kw] = in_s[ci][oyb + 8 + kh][ox + kw];
                    }
                    #pragma unroll
                    for (int kw = 0; kw < 3; kw++) {
                        const float4 wA = *(const float4*)&w_s[(ci * 9 + kh * 3 + kw) * 8];
                        const float4 wB = *(const float4*)&w_s[(ci * 9 + kh * 3 + kw) * 8 + 4];
                        float wv[8] = {wA.x, wA.y, wA.z, wA.w, wB.x, wB.y, wB.z, wB.w};
                        #pragma unroll
                        for (int co = 0; co < CO_PB; co++) {
                            acc[co][0] = fmaf(i0[kw], wv[co], acc[co][0]);
                            acc[co][1] = fmaf(i1[kw], wv[co], acc[co][1]);
                        }
                    }
                }
            }
        }

        // coalesced patch writes (warp spans 32 consecutive x)
        #pragma unroll
        for (int co = 0; co < CO_PB; co++) {
            float bv = bias[cob + co];
            #pragma unroll
            for (int p = 0; p < 2; p++) {
                int oy = ys + oyb + 8 * p;
                out[((b * COUT + cob + co) * H_ + (y0 + oy)) * W_ + (x0 + ox)] =
                    acc[co][p] + bv;
            }
        }
    } else {
        // ------------- copy path: stale buffer, skip patch, MLP=4 -------------
        __shared__ int loc_s[2 * B_];
        if (tid < 2 * B_) loc_s[tid] = loc[tid];
        __syncthreads();

        const float4* src = (const float4*)prev;
        float4* dst = (float4*)out;
        const unsigned stride = (unsigned)COPY_BLOCKS * THREADS;
        const unsigned q0 = (unsigned)(bid - CONV_BLOCKS) * THREADS + tid;

        for (unsigned base = q0; base < (unsigned)TOTAL_F4; base += stride * 4u) {
            float4 v[4];
            unsigned qs[4];
            bool ok[4];
            #pragma unroll
            for (int e = 0; e < 4; e++) {
                qs[e] = base + (unsigned)e * stride;
                ok[e] = qs[e] < (unsigned)TOTAL_F4;
                if (ok[e]) v[e] = src[qs[e]];     // batched: 4 independent loads
            }
            #pragma unroll
            for (int e = 0; e < 4; e++) {
                if (!ok[e]) continue;
                unsigned q  = qs[e];
                unsigned x4 = q % 56u;
                unsigned t  = q / 56u;
                unsigned y  = t % 224u;
                unsigned bb = (t / 224u) >> 6;
                int y0 = loc_s[2 * bb];
                int x0 = loc_s[2 * bb + 1];
                int xlo = (int)(x4 * 4u);
                bool yin = ((int)y >= y0) && ((int)y < y0 + PH);
                if (!yin || (xlo + 3 < x0) || (xlo >= x0 + PW)) {
                    dst[q] = v[e];                       // fully outside patch
                } else if (xlo >= x0 && xlo + 3 < x0 + PW) {
                    // fully inside patch: conv owns it
                } else {
                    float vv[4] = {v[e].x, v[e].y, v[e].z, v[e].w};
                    #pragma unroll
                    for (int k = 0; k < 4; k++) {
                        int x = xlo + k;
                        if (x < x0 || x >= x0 + PW) out[q * 4u + k] = vv[k];
                    }
                }
            }
        }
    }
}

extern "C" void kernel_launch(void* const* d_in, const int* in_sizes, int n_in,
                              void* d_out, int out_size) {
    const float* in   = (const float*)d_in[0];
    const float* wgt  = (const float*)d_in[1];
    const float* bias = (const float*)d_in[2];
    const float* prev = (const float*)d_in[3];
    const int*   loc  = (const int*)d_in[4];
    float* out = (float*)d_out;

    inc_conv_fused<<<CONV_BLOCKS + COPY_BLOCKS, THREADS>>>(in, wgt, bias, prev, loc, out);
}

// round 6
// speedup vs baseline: 1.0076x; 1.0076x over previous
#include <cuda_runtime.h>

// Problem constants (fixed by setup_inputs)
#define B_    16
#define CIN   64
#define COUT  64
#define H_    224
#define W_    224
#define PH    32
#define PW    32

#define THREADS 256
#define CO_PB 8                       // Cout per conv block
#define CONV_BLOCKS (B_ * (COUT / CO_PB) * 2)        // 256
#define COPY_BLOCKS 2112                              // total grid 2368 = 4 x 592
#define NROWS (B_ * COUT * H_)                        // 229376 rows of 224 floats
#define ROW_F4 56

#define ROWS_IN 18                    // 16 output rows + 2 halo
#define ROW_S  36                     // padded smem row stride
#define IN_SMEM (8 * ROWS_IN * ROW_S) // 5184 floats
#define W_SMEM  (8 * 8 * 9)           // 576 floats, layout [ci][k][co]

__device__ __forceinline__ void store_row_patch(float4* __restrict__ d, int q,
                                                float4 v, int x0)
{
    int xlo = q * 4;
    if (xlo + 3 < x0 || xlo >= x0 + PW) {
        d[q] = v;                                   // fully outside patch-x
    } else if (xlo >= x0 && xlo + 3 < x0 + PW) {
        // fully inside: conv block owns it
    } else {
        float vv[4] = {v.x, v.y, v.z, v.w};
        #pragma unroll
        for (int k = 0; k < 4; k++) {
            int x = xlo + k;
            if (x < x0 || x >= x0 + PW) ((float*)d)[xlo + k] = vv[k];
        }
    }
}

__device__ __forceinline__ void process_row(float4* __restrict__ dst, int r,
                                            int lane, float4 v0, float4 v1,
                                            const int* loc_s)
{
    unsigned b = (unsigned)r / 14336u;              // rows per batch = 64*224
    unsigned y = (unsigned)r % 224u;
    int y0 = loc_s[2 * b];
    float4* d = dst + (size_t)r * ROW_F4;
    if (y < (unsigned)y0 || y >= (unsigned)(y0 + PH)) {
        d[lane] = v0;                               // uniform fast path
        if (lane < 24) d[32 + lane] = v1;
    } else {
        int x0 = loc_s[2 * b + 1];
        store_row_patch(d, lane, v0, x0);
        if (lane < 24) store_row_patch(d, 32 + lane, v1, x0);
    }
}

__global__ __launch_bounds__(THREADS, 4)
void inc_conv_fused(const float* __restrict__ in,
                    const float* __restrict__ wgt,
                    const float* __restrict__ bias,
                    const float* __restrict__ prev,
                    const int*   __restrict__ loc,
                    float* __restrict__ out)
{
    __shared__ float smem[IN_SMEM + W_SMEM];
    const int tid = threadIdx.x;
    const int bid = blockIdx.x;

    if (bid < CONV_BLOCKS) {
        // ------------- conv path: block = (batch, 8 Cout, 16-row half) -------------
        float (*in_s)[ROWS_IN][ROW_S] = (float (*)[ROWS_IN][ROW_S])smem;
        float* w_s = smem + IN_SMEM;

        const int b   = bid >> 4;
        const int rem = bid & 15;
        const int cob = (rem >> 1) * CO_PB;
        const int ys  = (rem & 1) * 16;
        const int y0  = loc[2 * b];
        const int x0  = loc[2 * b + 1];

        float acc[CO_PB][2];
        #pragma unroll
        for (int co = 0; co < CO_PB; co++) { acc[co][0] = 0.f; acc[co][1] = 0.f; }

        const int oyb = tid >> 5;   // 0..7
        const int ox  = tid & 31;   // 0..31

        for (int ci0 = 0; ci0 < CIN; ci0 += 8) {
            __syncthreads();
            // stage input: 8ci x 18 x 34 (only low padded edges can underflow)
            for (int i = tid; i < 8 * ROWS_IN * 34; i += THREADS) {
                int ci = i / (ROWS_IN * 34);
                int rr = i % (ROWS_IN * 34);
                int r = rr / 34, c = rr % 34;
                int iy = y0 - 1 + ys + r;
                int ix = x0 - 1 + c;
                float v = 0.f;
                if (iy >= 0 && ix >= 0)
                    v = in[(((b * CIN) + ci0 + ci) * H_ + iy) * W_ + ix];
                in_s[ci][r][c] = v;
            }
            // stage weights transposed: w_s[(ci*9 + k)*8 + co]
            for (int i = tid; i < W_SMEM; i += THREADS) {
                int co = i & 7;
                int k  = (i >> 3) % 9;
                int ci = i / 72;
                w_s[(ci * 9 + k) * 8 + co] =
                    wgt[((cob + co) * CIN + ci0 + ci) * 9 + k];
            }
            __syncthreads();

            #pragma unroll
            for (int ci = 0; ci < 8; ci++) {
                #pragma unroll
                for (int kh = 0; kh < 3; kh++) {
                    float i0[3], i1[3];
                    #pragma unroll
                    for (int kw = 0; kw < 3; kw++) {
                        i0[kw] = in_s[ci][oyb + kh][ox + kw];
                        i1[kw] = in_s[ci][oyb + 8 + kh][ox + kw];
                    }
                    #pragma unroll
                    for (int kw = 0; kw < 3; kw++) {
                        const float4 wA = *(const float4*)&w_s[(ci * 9 + kh * 3 + kw) * 8];
                        const float4 wB = *(const float4*)&w_s[(ci * 9 + kh * 3 + kw) * 8 + 4];
                        float wv[8] = {wA.x, wA.y, wA.z, wA.w, wB.x, wB.y, wB.z, wB.w};
                        #pragma unroll
                        for (int co = 0; co < CO_PB; co++) {
                            acc[co][0] = fmaf(i0[kw], wv[co], acc[co][0]);
                            acc[co][1] = fmaf(i1[kw], wv[co], acc[co][1]);
                        }
                    }
                }
            }
        }

        // coalesced patch writes (warp spans 32 consecutive x)
        #pragma unroll
        for (int co = 0; co < CO_PB; co++) {
            float bv = bias[cob + co];
            #pragma unroll
            for (int p = 0; p < 2; p++) {
                int oy = ys + oyb + 8 * p;
                out[((b * COUT + cob + co) * H_ + (y0 + oy)) * W_ + (x0 + ox)] =
                    acc[co][p] + bv;
            }
        }
    } else {
        // ------------- copy path: one warp per 224-float row, row-pair MLP -------------
        __shared__ int loc_s[2 * B_];
        if (tid < 2 * B_) loc_s[tid] = loc[tid];
        __syncthreads();

        const int lane = tid & 31;
        const int gw = (bid - CONV_BLOCKS) * (THREADS / 32) + (tid >> 5);
        const int NW = COPY_BLOCKS * (THREADS / 32);     // 16896 warps

        const float4* src = (const float4*)prev;
        float4* dst = (float4*)out;

        for (int r = gw; r < NROWS; r += 2 * NW) {
            const int r1 = r + NW;
            const bool has2 = (r1 < NROWS);

            // batched loads: up to 4 independent LDG.128 in flight
            const float4* s0 = src + (size_t)r * ROW_F4;
            float4 a0 = s0[lane];
            float4 a1; if (lane < 24) a1 = s0[32 + lane];
            float4 b0, b1;
            if (has2) {
                const float4* s1 = src + (size_t)r1 * ROW_F4;
                b0 = s1[lane];
                if (lane < 24) b1 = s1[32 + lane];
            }

            process_row(dst, r, lane, a0, a1, loc_s);
            if (has2) process_row(dst, r1, lane, b0, b1, loc_s);
        }
    }
}

extern "C" void kernel_launch(void* const* d_in, const int* in_sizes, int n_in,
                              void* d_out, int out_size) {
    const float* in   = (const float*)d_in[0];
    const float* wgt  = (const float*)d_in[1];
    const float* bias = (const float*)d_in[2];
    const float* prev = (const float*)d_in[3];
    const int*   loc  = (const int*)d_in[4];
    float* out = (float*)d_out;

    inc_conv_fused<<<CONV_BLOCKS + COPY_BLOCKS, THREADS>>>(in, wgt, bias, prev, loc, out);
}